// round 1
// baseline (speedup 1.0000x reference)
#include <cuda_runtime.h>
#include <math.h>

// Problem shape (fixed by dataset): B=8, T=4096, F=1024
#define B_DIM 8
#define T_DIM 4096
#define F_DIM 1024
#define F4 (F_DIM / 4)          // 256 float4 per row
#define ROWS_PER_BLK 64         // kernel1 chunk

// Scratch (no allocations allowed)
__device__ float g_ksum[B_DIM * F_DIM];
__device__ float g_kc[B_DIM * F_DIM];
__device__ float g_invkd[B_DIM];

// ---------------------------------------------------------------------------
__global__ void zero_scratch_kernel() {
    int i = blockIdx.x * blockDim.x + threadIdx.x;
    if (i < B_DIM * F_DIM) g_ksum[i] = 0.0f;
}

// ---------------------------------------------------------------------------
// Kernel 1: per-batch per-channel masked sum over T.
// grid (T/ROWS_PER_BLK, B), 256 threads; thread tid owns channels [4*tid, 4*tid+4)
__global__ void k_reduce_kernel(const float4* __restrict__ x,
                                const int* __restrict__ mask) {
    const int b = blockIdx.y;
    const int t0 = blockIdx.x * ROWS_PER_BLK;
    const int f4 = threadIdx.x;

    __shared__ int smask[ROWS_PER_BLK];
    if (threadIdx.x < ROWS_PER_BLK)
        smask[threadIdx.x] = mask[b * T_DIM + t0 + threadIdx.x];
    __syncthreads();

    const float4* xb = x + (size_t)b * T_DIM * F4;
    float ax = 0.f, ay = 0.f, az = 0.f, aw = 0.f;

    #pragma unroll 4
    for (int r = 0; r < ROWS_PER_BLK; ++r) {
        if (smask[r]) {
            float4 v = xb[(size_t)(t0 + r) * F4 + f4];
            ax += v.x; ay += v.y; az += v.z; aw += v.w;
        }
    }
    float* dst = &g_ksum[b * F_DIM + f4 * 4];
    atomicAdd(dst + 0, ax);
    atomicAdd(dst + 1, ay);
    atomicAdd(dst + 2, az);
    atomicAdd(dst + 3, aw);
}

// ---------------------------------------------------------------------------
__device__ __forceinline__ float block_reduce1(float v) {
    __shared__ float sh[8];
    #pragma unroll
    for (int o = 16; o; o >>= 1) v += __shfl_xor_sync(0xffffffffu, v, o);
    int w = threadIdx.x >> 5, l = threadIdx.x & 31;
    if (l == 0) sh[w] = v;
    __syncthreads();
    if (w == 0) {
        v = (l < 8) ? sh[l] : 0.f;
        #pragma unroll
        for (int o = 4; o; o >>= 1) v += __shfl_xor_sync(0xffffffffu, v, o);
        if (l == 0) sh[0] = v;
    }
    __syncthreads();
    float r = sh[0];
    __syncthreads();
    return r;
}

// Kernel 2: per batch: L, k = ksum/L, center over channels, kd. grid(B), 256 thr.
__global__ void k_stats_kernel(const int* __restrict__ mask) {
    const int b = blockIdx.x;
    const int tid = threadIdx.x;

    // L = sum of mask
    float lf = 0.f;
    for (int t = tid; t < T_DIM; t += 256) lf += (float)mask[b * T_DIM + t];
    float L = block_reduce1(lf);
    float invL = 1.0f / L;

    // k values for this thread's 4 channels
    float kv[4];
    float s = 0.f;
    #pragma unroll
    for (int j = 0; j < 4; ++j) {
        kv[j] = g_ksum[b * F_DIM + tid * 4 + j] * invL;
        s += kv[j];
    }
    float meank = block_reduce1(s) * (1.0f / (float)F_DIM);

    float ss = 0.f;
    #pragma unroll
    for (int j = 0; j < 4; ++j) {
        float kc = kv[j] - meank;
        g_kc[b * F_DIM + tid * 4 + j] = kc;
        ss += kc * kc;
    }
    float kd2 = block_reduce1(ss);
    if (tid == 0) g_invkd[b] = rsqrtf(kd2);
}

// ---------------------------------------------------------------------------
__device__ __forceinline__ void block_reduce3(float& a, float& b, float& c) {
    __shared__ float sa[8], sb[8], sc[8];
    #pragma unroll
    for (int o = 16; o; o >>= 1) {
        a += __shfl_xor_sync(0xffffffffu, a, o);
        b += __shfl_xor_sync(0xffffffffu, b, o);
        c += __shfl_xor_sync(0xffffffffu, c, o);
    }
    int w = threadIdx.x >> 5, l = threadIdx.x & 31;
    if (l == 0) { sa[w] = a; sb[w] = b; sc[w] = c; }
    __syncthreads();
    if (w == 0) {
        a = (l < 8) ? sa[l] : 0.f;
        b = (l < 8) ? sb[l] : 0.f;
        c = (l < 8) ? sc[l] : 0.f;
        #pragma unroll
        for (int o = 4; o; o >>= 1) {
            a += __shfl_xor_sync(0xffffffffu, a, o);
            b += __shfl_xor_sync(0xffffffffu, b, o);
            c += __shfl_xor_sync(0xffffffffu, c, o);
        }
        if (l == 0) { sa[0] = a; sb[0] = b; sc[0] = c; }
    }
    __syncthreads();
    a = sa[0]; b = sb[0]; c = sc[0];
}

// Kernel 3: one block per (b,t) row. grid (T, B), 256 threads.
// num = dot(x, k_centered); qd^2 = sumsq - sum^2/F; A = 1/(1+exp(C)); out = x*A*m
__global__ void pfsa_out_kernel(const float4* __restrict__ x,
                                const int* __restrict__ mask,
                                float4* __restrict__ out) {
    const int t = blockIdx.x;
    const int b = blockIdx.y;
    const int f4 = threadIdx.x;
    const size_t base = ((size_t)b * T_DIM + t) * F4;

    if (!mask[b * T_DIM + t]) {
        out[base + f4] = make_float4(0.f, 0.f, 0.f, 0.f);
        return;  // uniform per block: no divergence across the __syncthreads below
    }

    float4 v = x[base + f4];
    const float4 kc = *(const float4*)&g_kc[b * F_DIM + f4 * 4];

    float s1 = v.x + v.y + v.z + v.w;
    float s2 = v.x * v.x + v.y * v.y + v.z * v.z + v.w * v.w;
    float s3 = v.x * kc.x + v.y * kc.y + v.z * kc.z + v.w * kc.w;

    block_reduce3(s1, s2, s3);

    float qd2 = s2 - s1 * s1 * (1.0f / (float)F_DIM);
    float C = s3 * rsqrtf(qd2) * g_invkd[b];
    float A = 1.0f / (1.0f + expf(C));   // (1 - sigmoid(C))^1

    v.x *= A; v.y *= A; v.z *= A; v.w *= A;
    out[base + f4] = v;
}

// ---------------------------------------------------------------------------
extern "C" void kernel_launch(void* const* d_in, const int* in_sizes, int n_in,
                              void* d_out, int out_size) {
    const float4* x = (const float4*)d_in[0];
    const int* mask = (const int*)d_in[1];
    float4* out = (float4*)d_out;

    zero_scratch_kernel<<<(B_DIM * F_DIM + 255) / 256, 256>>>();

    dim3 g1(T_DIM / ROWS_PER_BLK, B_DIM);
    k_reduce_kernel<<<g1, 256>>>(x, mask);

    k_stats_kernel<<<B_DIM, 256>>>(mask);

    dim3 g3(T_DIM, B_DIM);
    pfsa_out_kernel<<<g3, 256>>>(x, mask, out);
}

// round 2
// speedup vs baseline: 1.2119x; 1.2119x over previous
#include <cuda_runtime.h>
#include <math.h>

// Problem shape (fixed by dataset): B=8, T=4096, F=1024
#define B_DIM 8
#define T_DIM 4096
#define F_DIM 1024
#define F4 (F_DIM / 4)          // 256 float4 per row
#define ROWS_PER_BLK 64         // kernel1 chunk

// Scratch (no allocations allowed)
__device__ float g_ksum[B_DIM * F_DIM];
__device__ float g_kc[B_DIM * F_DIM];
__device__ float g_invkd[B_DIM];

// ---------------------------------------------------------------------------
__global__ void zero_scratch_kernel() {
    int i = blockIdx.x * blockDim.x + threadIdx.x;
    if (i < B_DIM * F_DIM) g_ksum[i] = 0.0f;
}

// ---------------------------------------------------------------------------
// Kernel 1: per-batch per-channel masked sum over T. Forward scan (warms L2
// with the tail of x for kernel 3's reverse scan).
// grid (T/ROWS_PER_BLK, B), 256 threads; thread tid owns channels [4*tid, 4*tid+4)
__global__ void k_reduce_kernel(const float4* __restrict__ x,
                                const int* __restrict__ mask) {
    const int b = blockIdx.y;
    const int t0 = blockIdx.x * ROWS_PER_BLK;
    const int f4 = threadIdx.x;

    __shared__ int smask[ROWS_PER_BLK];
    if (threadIdx.x < ROWS_PER_BLK)
        smask[threadIdx.x] = mask[b * T_DIM + t0 + threadIdx.x];
    __syncthreads();

    const float4* xb = x + (size_t)b * T_DIM * F4;
    float ax = 0.f, ay = 0.f, az = 0.f, aw = 0.f;

    #pragma unroll 4
    for (int r = 0; r < ROWS_PER_BLK; ++r) {
        if (smask[r]) {
            float4 v = xb[(size_t)(t0 + r) * F4 + f4];
            ax += v.x; ay += v.y; az += v.z; aw += v.w;
        }
    }
    float* dst = &g_ksum[b * F_DIM + f4 * 4];
    atomicAdd(dst + 0, ax);
    atomicAdd(dst + 1, ay);
    atomicAdd(dst + 2, az);
    atomicAdd(dst + 3, aw);
}

// ---------------------------------------------------------------------------
__device__ __forceinline__ float block_reduce1(float v) {
    __shared__ float sh[8];
    #pragma unroll
    for (int o = 16; o; o >>= 1) v += __shfl_xor_sync(0xffffffffu, v, o);
    int w = threadIdx.x >> 5, l = threadIdx.x & 31;
    if (l == 0) sh[w] = v;
    __syncthreads();
    if (w == 0) {
        v = (l < 8) ? sh[l] : 0.f;
        #pragma unroll
        for (int o = 4; o; o >>= 1) v += __shfl_xor_sync(0xffffffffu, v, o);
        if (l == 0) sh[0] = v;
    }
    __syncthreads();
    float r = sh[0];
    __syncthreads();
    return r;
}

// Kernel 2: per batch: L, k = ksum/L, center over channels, kd. grid(B), 256 thr.
__global__ void k_stats_kernel(const int* __restrict__ mask) {
    const int b = blockIdx.x;
    const int tid = threadIdx.x;

    float lf = 0.f;
    for (int t = tid; t < T_DIM; t += 256) lf += (float)mask[b * T_DIM + t];
    float L = block_reduce1(lf);
    float invL = 1.0f / L;

    float kv[4];
    float s = 0.f;
    #pragma unroll
    for (int j = 0; j < 4; ++j) {
        kv[j] = g_ksum[b * F_DIM + tid * 4 + j] * invL;
        s += kv[j];
    }
    float meank = block_reduce1(s) * (1.0f / (float)F_DIM);

    float ss = 0.f;
    #pragma unroll
    for (int j = 0; j < 4; ++j) {
        float kc = kv[j] - meank;
        g_kc[b * F_DIM + tid * 4 + j] = kc;
        ss += kc * kc;
    }
    float kd2 = block_reduce1(ss);
    if (tid == 0) g_invkd[b] = rsqrtf(kd2);
}

// ---------------------------------------------------------------------------
// Kernel 3: WARP-PER-ROW. Block = 256 threads = 8 warps = 8 rows.
// Each thread holds 8 float4 of the row (256 f4 / 32 lanes). No block
// barriers; 3-way warp shuffle reduce only. Rows walked in REVERSE global
// order to hit the x tail that kernel 1 left resident in L2.
__global__ void __launch_bounds__(256) pfsa_out_kernel(
        const float4* __restrict__ x,
        const int* __restrict__ mask,
        float4* __restrict__ out) {
    const int warp = threadIdx.x >> 5;
    const int lane = threadIdx.x & 31;

    // reverse row order
    const int row = (B_DIM * T_DIM - 1) - (blockIdx.x * 8 + warp);
    const int b = row >> 12;            // row / T_DIM
    const int t = row & (T_DIM - 1);    // row % T_DIM

    const size_t base = (size_t)row * F4;

    if (!mask[b * T_DIM + t]) {
        const float4 z = make_float4(0.f, 0.f, 0.f, 0.f);
        #pragma unroll
        for (int j = 0; j < 8; ++j)
            out[base + lane + j * 32] = z;
        return;
    }

    // Front-batched loads: 8 x-loads + 8 kc-loads, all independent (MLP=16)
    float4 v[8], kc[8];
    const float4* kcb = (const float4*)&g_kc[b * F_DIM];
    #pragma unroll
    for (int j = 0; j < 8; ++j) v[j] = x[base + lane + j * 32];
    #pragma unroll
    for (int j = 0; j < 8; ++j) kc[j] = kcb[lane + j * 32];

    float s1 = 0.f, s2 = 0.f, s3 = 0.f;
    #pragma unroll
    for (int j = 0; j < 8; ++j) {
        s1 += v[j].x + v[j].y + v[j].z + v[j].w;
        s2 += v[j].x * v[j].x + v[j].y * v[j].y + v[j].z * v[j].z + v[j].w * v[j].w;
        s3 += v[j].x * kc[j].x + v[j].y * kc[j].y + v[j].z * kc[j].z + v[j].w * kc[j].w;
    }

    #pragma unroll
    for (int o = 16; o; o >>= 1) {
        s1 += __shfl_xor_sync(0xffffffffu, s1, o);
        s2 += __shfl_xor_sync(0xffffffffu, s2, o);
        s3 += __shfl_xor_sync(0xffffffffu, s3, o);
    }

    float qd2 = s2 - s1 * s1 * (1.0f / (float)F_DIM);
    float C = s3 * rsqrtf(qd2) * g_invkd[b];
    float A = 1.0f / (1.0f + __expf(C));   // (1 - sigmoid(C))^ALPHA, ALPHA=1

    #pragma unroll
    for (int j = 0; j < 8; ++j) {
        v[j].x *= A; v[j].y *= A; v[j].z *= A; v[j].w *= A;
        out[base + lane + j * 32] = v[j];
    }
}

// ---------------------------------------------------------------------------
extern "C" void kernel_launch(void* const* d_in, const int* in_sizes, int n_in,
                              void* d_out, int out_size) {
    const float4* x = (const float4*)d_in[0];
    const int* mask = (const int*)d_in[1];
    float4* out = (float4*)d_out;

    zero_scratch_kernel<<<(B_DIM * F_DIM + 255) / 256, 256>>>();

    dim3 g1(T_DIM / ROWS_PER_BLK, B_DIM);
    k_reduce_kernel<<<g1, 256>>>(x, mask);

    k_stats_kernel<<<B_DIM, 256>>>(mask);

    pfsa_out_kernel<<<(B_DIM * T_DIM) / 8, 256>>>(x, mask, out);
}

// round 3
// speedup vs baseline: 1.3037x; 1.0758x over previous
#include <cuda_runtime.h>
#include <math.h>

// Problem shape (fixed by dataset): B=8, T=4096, F=1024
#define B_DIM 8
#define T_DIM 4096
#define F_DIM 1024
#define F4 (F_DIM / 4)          // 256 float4 per row
#define ROWS_PER_BLK 64         // kernel1 chunk

// Scratch (no allocations allowed)
__device__ float g_ksum[B_DIM * F_DIM];
__device__ float g_kc[B_DIM * F_DIM];
__device__ float g_invkd[B_DIM];

// ---------------------------------------------------------------------------
__global__ void zero_scratch_kernel() {
    int i = blockIdx.x * blockDim.x + threadIdx.x;
    if (i < B_DIM * F_DIM) g_ksum[i] = 0.0f;
}

// ---------------------------------------------------------------------------
// Kernel 1: per-batch per-channel masked sum over T. Forward scan (warms L2
// with the tail of x for kernel 3's reverse scan). Default load policy so
// the data STAYS in L2.
// grid (T/ROWS_PER_BLK, B), 256 threads; thread tid owns channels [4*tid, 4*tid+4)
__global__ void __launch_bounds__(256) k_reduce_kernel(
        const float4* __restrict__ x,
        const int* __restrict__ mask) {
    const int b = blockIdx.y;
    const int t0 = blockIdx.x * ROWS_PER_BLK;
    const int f4 = threadIdx.x;

    __shared__ int smask[ROWS_PER_BLK];
    if (threadIdx.x < ROWS_PER_BLK)
        smask[threadIdx.x] = mask[b * T_DIM + t0 + threadIdx.x];
    __syncthreads();

    const float4* xb = x + (size_t)b * T_DIM * F4 + (size_t)t0 * F4 + f4;
    float ax = 0.f, ay = 0.f, az = 0.f, aw = 0.f;

    #pragma unroll 8
    for (int r = 0; r < ROWS_PER_BLK; ++r) {
        if (smask[r]) {
            float4 v = xb[(size_t)r * F4];
            ax += v.x; ay += v.y; az += v.z; aw += v.w;
        }
    }
    float* dst = &g_ksum[b * F_DIM + f4 * 4];
    atomicAdd(dst + 0, ax);
    atomicAdd(dst + 1, ay);
    atomicAdd(dst + 2, az);
    atomicAdd(dst + 3, aw);
}

// ---------------------------------------------------------------------------
__device__ __forceinline__ float block_reduce1(float v) {
    __shared__ float sh[8];
    #pragma unroll
    for (int o = 16; o; o >>= 1) v += __shfl_xor_sync(0xffffffffu, v, o);
    int w = threadIdx.x >> 5, l = threadIdx.x & 31;
    if (l == 0) sh[w] = v;
    __syncthreads();
    if (w == 0) {
        v = (l < 8) ? sh[l] : 0.f;
        #pragma unroll
        for (int o = 4; o; o >>= 1) v += __shfl_xor_sync(0xffffffffu, v, o);
        if (l == 0) sh[0] = v;
    }
    __syncthreads();
    float r = sh[0];
    __syncthreads();
    return r;
}

// Kernel 2: per batch: L, k = ksum/L, center over channels, kd. grid(B), 256 thr.
__global__ void k_stats_kernel(const int* __restrict__ mask) {
    const int b = blockIdx.x;
    const int tid = threadIdx.x;

    float lf = 0.f;
    for (int t = tid; t < T_DIM; t += 256) lf += (float)mask[b * T_DIM + t];
    float L = block_reduce1(lf);
    float invL = 1.0f / L;

    float kv[4];
    float s = 0.f;
    #pragma unroll
    for (int j = 0; j < 4; ++j) {
        kv[j] = g_ksum[b * F_DIM + tid * 4 + j] * invL;
        s += kv[j];
    }
    float meank = block_reduce1(s) * (1.0f / (float)F_DIM);

    float ss = 0.f;
    #pragma unroll
    for (int j = 0; j < 4; ++j) {
        float kc = kv[j] - meank;
        g_kc[b * F_DIM + tid * 4 + j] = kc;
        ss += kc * kc;
    }
    float kd2 = block_reduce1(ss);
    if (tid == 0) g_invkd[b] = rsqrtf(kd2);
}

// ---------------------------------------------------------------------------
// Kernel 3: WARP-PER-ROW. Block = 256 threads = 8 warps = 8 rows.
// Rows walked in REVERSE global order to hit the x tail left in L2 by
// kernel 1. x read with .cs (last use), out written with .cs (never re-read)
// so pass-3 traffic does not evict the still-needed x head/tail from L2.
__global__ void __launch_bounds__(256) pfsa_out_kernel(
        const float4* __restrict__ x,
        const int* __restrict__ mask,
        float4* __restrict__ out) {
    const int warp = threadIdx.x >> 5;
    const int lane = threadIdx.x & 31;

    // reverse row order
    const int row = (B_DIM * T_DIM - 1) - (blockIdx.x * 8 + warp);
    const int b = row >> 12;            // row / T_DIM
    const int t = row & (T_DIM - 1);    // row % T_DIM

    const size_t base = (size_t)row * F4;

    if (!mask[b * T_DIM + t]) {
        const float4 z = make_float4(0.f, 0.f, 0.f, 0.f);
        #pragma unroll
        for (int j = 0; j < 8; ++j)
            __stcs(&out[base + lane + j * 32], z);
        return;
    }

    // Front-batched x loads: 8 independent float4 (streaming / last-use)
    float4 v[8];
    #pragma unroll
    for (int j = 0; j < 8; ++j) v[j] = __ldcs(&x[base + lane + j * 32]);

    float s1 = 0.f, s2 = 0.f;
    #pragma unroll
    for (int j = 0; j < 8; ++j) {
        s1 += v[j].x + v[j].y + v[j].z + v[j].w;
        s2 += v[j].x * v[j].x + v[j].y * v[j].y + v[j].z * v[j].z + v[j].w * v[j].w;
    }

    // kc dot in two 4-wide chunks (kc is L1-resident: 4KB per batch, massive reuse)
    const float4* kcb = (const float4*)&g_kc[b * F_DIM];
    float s3 = 0.f;
    #pragma unroll
    for (int h = 0; h < 2; ++h) {
        float4 kc[4];
        #pragma unroll
        for (int j = 0; j < 4; ++j) kc[j] = kcb[lane + (h * 4 + j) * 32];
        #pragma unroll
        for (int j = 0; j < 4; ++j) {
            const float4& w = v[h * 4 + j];
            s3 += w.x * kc[j].x + w.y * kc[j].y + w.z * kc[j].z + w.w * kc[j].w;
        }
    }

    #pragma unroll
    for (int o = 16; o; o >>= 1) {
        s1 += __shfl_xor_sync(0xffffffffu, s1, o);
        s2 += __shfl_xor_sync(0xffffffffu, s2, o);
        s3 += __shfl_xor_sync(0xffffffffu, s3, o);
    }

    float qd2 = s2 - s1 * s1 * (1.0f / (float)F_DIM);
    float C = s3 * rsqrtf(qd2) * g_invkd[b];
    float A = 1.0f / (1.0f + __expf(C));   // (1 - sigmoid(C))^ALPHA, ALPHA=1

    #pragma unroll
    for (int j = 0; j < 8; ++j) {
        v[j].x *= A; v[j].y *= A; v[j].z *= A; v[j].w *= A;
        __stcs(&out[base + lane + j * 32], v[j]);
    }
}

// ---------------------------------------------------------------------------
extern "C" void kernel_launch(void* const* d_in, const int* in_sizes, int n_in,
                              void* d_out, int out_size) {
    const float4* x = (const float4*)d_in[0];
    const int* mask = (const int*)d_in[1];
    float4* out = (float4*)d_out;

    zero_scratch_kernel<<<(B_DIM * F_DIM + 255) / 256, 256>>>();

    dim3 g1(T_DIM / ROWS_PER_BLK, B_DIM);
    k_reduce_kernel<<<g1, 256>>>(x, mask);

    k_stats_kernel<<<B_DIM, 256>>>(mask);

    pfsa_out_kernel<<<(B_DIM * T_DIM) / 8, 256>>>(x, mask, out);
}